// round 1
// baseline (speedup 1.0000x reference)
#include <cuda_runtime.h>
#include <cuda_bf16.h>
#include <math.h>

// ---------------------------------------------------------------------------
// Problem dims (fixed): B=4, Q=K=4096, D=IN=256
// Pipeline:
//   q = queries@Wq^T+bq ; k = keys@Wk^T+bk ; v = values@Wv^T+bv
//   S = q@k^T ; S = where(valid, S, -1e9)/16 ; P = softmax(S)
//   att = P@v ; out = att@Wo^T + bo
// ---------------------------------------------------------------------------

#define BM 128
#define BN 128
#define BK 8
#define TM 8
#define TN 8

// Scratch (static __device__ arrays: allocation-guard safe)
__device__ float g_q[4u * 4096u * 256u];
__device__ float g_k[4u * 4096u * 256u];
__device__ float g_v[4u * 4096u * 256u];
__device__ float g_att[4u * 4096u * 256u];
__device__ float g_scores[67108864u];  // 4*4096*4096 fp32 = 256 MB

// ---------------------------------------------------------------------------
// Generic fp32 SGEMM:
//   C[M,N] = A[M,Kd] * op(B) (+ bias)
//   TRANSB=true : B is [N,Kd] row-major (C = A * B^T)
//   TRANSB=false: B is [Kd,N] row-major (C = A * B)
// Batched over blockIdx.z with element strides sA/sB/sC.
// Requires: M%128==0, N%128==0, Kd%8==0 (true for all shapes here).
// ---------------------------------------------------------------------------
template <bool TRANSB, bool BIAS>
__global__ __launch_bounds__(256) void sgemm_kernel(
    const float* __restrict__ A, const float* __restrict__ B,
    const float* __restrict__ bias, float* __restrict__ C,
    int M, int N, int Kd, long long sA, long long sB, long long sC) {
  __shared__ float As[BK][BM];
  __shared__ float Bs[BK][BN];

  A += (long long)blockIdx.z * sA;
  B += (long long)blockIdx.z * sB;
  C += (long long)blockIdx.z * sC;

  const int bm = blockIdx.y * BM;
  const int bn = blockIdx.x * BN;
  const int t = threadIdx.x;
  const int tx = t & 15;   // 0..15 -> N microtiles
  const int ty = t >> 4;   // 0..15 -> M microtiles

  // A-tile (and trans-B-tile) loader mapping: 128 rows x 8 cols, float4 each
  const int aRow = t >> 1;        // 0..127
  const int aCol = (t & 1) * 4;   // 0 or 4

  float acc[TM][TN];
#pragma unroll
  for (int i = 0; i < TM; i++)
#pragma unroll
    for (int j = 0; j < TN; j++) acc[i][j] = 0.0f;

  for (int k0 = 0; k0 < Kd; k0 += BK) {
    // load A tile (transposed into smem: As[k][m])
    float4 av = *(const float4*)(A + (long long)(bm + aRow) * Kd + k0 + aCol);
    As[aCol + 0][aRow] = av.x;
    As[aCol + 1][aRow] = av.y;
    As[aCol + 2][aRow] = av.z;
    As[aCol + 3][aRow] = av.w;

    if (TRANSB) {
      float4 bv = *(const float4*)(B + (long long)(bn + aRow) * Kd + k0 + aCol);
      Bs[aCol + 0][aRow] = bv.x;
      Bs[aCol + 1][aRow] = bv.y;
      Bs[aCol + 2][aRow] = bv.z;
      Bs[aCol + 3][aRow] = bv.w;
    } else {
      const int bRow = t >> 5;          // 0..7
      const int bCol = (t & 31) * 4;    // 0..124
      float4 bv = *(const float4*)(B + (long long)(k0 + bRow) * N + bn + bCol);
      *(float4*)&Bs[bRow][bCol] = bv;
    }
    __syncthreads();

#pragma unroll
    for (int kk = 0; kk < BK; kk++) {
      float4 a0 = *(const float4*)&As[kk][ty * TM];
      float4 a1 = *(const float4*)&As[kk][ty * TM + 4];
      float4 b0 = *(const float4*)&Bs[kk][tx * TN];
      float4 b1 = *(const float4*)&Bs[kk][tx * TN + 4];
      float ar[8] = {a0.x, a0.y, a0.z, a0.w, a1.x, a1.y, a1.z, a1.w};
      float br[8] = {b0.x, b0.y, b0.z, b0.w, b1.x, b1.y, b1.z, b1.w};
#pragma unroll
      for (int i = 0; i < TM; i++)
#pragma unroll
        for (int j = 0; j < TN; j++) acc[i][j] += ar[i] * br[j];
    }
    __syncthreads();
  }

#pragma unroll
  for (int i = 0; i < TM; i++) {
    const long long row = bm + ty * TM + i;
#pragma unroll
    for (int j = 0; j < TN; j += 4) {
      const int col = bn + tx * TN + j;
      float4 o;
      o.x = acc[i][j + 0];
      o.y = acc[i][j + 1];
      o.z = acc[i][j + 2];
      o.w = acc[i][j + 3];
      if (BIAS) {
        o.x += bias[col + 0];
        o.y += bias[col + 1];
        o.z += bias[col + 2];
        o.w += bias[col + 3];
      }
      *(float4*)(C + row * N + col) = o;
    }
  }
}

// ---------------------------------------------------------------------------
// Fused length-mask + scale(1/16) + softmax, in place on the scores buffer.
// One block per (b,q) row of 4096 keys. Invalid keys -> prob exactly 0
// (matches reference: exp((-1e9/16) - max) underflows to 0 in fp32).
// ---------------------------------------------------------------------------
__global__ __launch_bounds__(256) void softmax_mask_kernel(
    float* __restrict__ scores, const int* __restrict__ mask) {
  const size_t row = blockIdx.x;
  const int len = mask[row];
  float* r = scores + row * 4096u;
  const int t = threadIdx.x;
  const int lane = t & 31;
  const int wid = t >> 5;

  __shared__ float sred[8];

  const float scale = 0.0625f;  // 1/sqrt(256)
  float v[16];
  float mx = -1e30f;
#pragma unroll
  for (int i = 0; i < 16; i++) {
    const int kk = t + i * 256;  // coalesced
    float s = (kk < len) ? r[kk] * scale : -1e30f;
    v[i] = s;
    mx = fmaxf(mx, s);
  }
  // block max
#pragma unroll
  for (int o = 16; o; o >>= 1) mx = fmaxf(mx, __shfl_xor_sync(0xffffffffu, mx, o));
  if (lane == 0) sred[wid] = mx;
  __syncthreads();
  float bm = sred[0];
#pragma unroll
  for (int w = 1; w < 8; w++) bm = fmaxf(bm, sred[w]);
  __syncthreads();

  float e[16];
  float sum = 0.0f;
#pragma unroll
  for (int i = 0; i < 16; i++) {
    e[i] = __expf(v[i] - bm);  // -1e30 - bm -> underflow -> exactly 0
    sum += e[i];
  }
#pragma unroll
  for (int o = 16; o; o >>= 1) sum += __shfl_xor_sync(0xffffffffu, sum, o);
  if (lane == 0) sred[wid] = sum;
  __syncthreads();
  float bs = 0.0f;
#pragma unroll
  for (int w = 0; w < 8; w++) bs += sred[w];
  const float inv = 1.0f / bs;

#pragma unroll
  for (int i = 0; i < 16; i++) {
    const int kk = t + i * 256;
    r[kk] = e[i] * inv;
  }
}

// ---------------------------------------------------------------------------
// Launch
// ---------------------------------------------------------------------------
extern "C" void kernel_launch(void* const* d_in, const int* in_sizes, int n_in,
                              void* d_out, int out_size) {
  const float* queries = (const float*)d_in[0];
  const float* keys    = (const float*)d_in[1];
  const float* values  = (const float*)d_in[2];
  const int*   mask    = (const int*)d_in[3];
  const float* Wq = (const float*)d_in[4];
  const float* bq = (const float*)d_in[5];
  const float* Wk = (const float*)d_in[6];
  const float* bk = (const float*)d_in[7];
  const float* Wv = (const float*)d_in[8];
  const float* bv = (const float*)d_in[9];
  const float* Wo = (const float*)d_in[10];
  const float* bo = (const float*)d_in[11];
  float* out = (float*)d_out;

  float *q, *k, *v, *att, *sc;
  cudaGetSymbolAddress((void**)&q, g_q);
  cudaGetSymbolAddress((void**)&k, g_k);
  cudaGetSymbolAddress((void**)&v, g_v);
  cudaGetSymbolAddress((void**)&att, g_att);
  cudaGetSymbolAddress((void**)&sc, g_scores);

  const int Bb = 4, Qn = 4096, Kn = 4096, Dn = 256, INn = 256;
  const int Mtok = Bb * Qn;  // 16384

  dim3 blk(256);

  // Input projections: X[16384,256] @ W^T[256,256] + b
  dim3 gProj(Dn / BN, Mtok / BM, 1);
  sgemm_kernel<true, true><<<gProj, blk>>>(queries, Wq, bq, q, Mtok, Dn, INn, 0, 0, 0);
  sgemm_kernel<true, true><<<gProj, blk>>>(keys,    Wk, bk, k, Mtok, Dn, INn, 0, 0, 0);
  sgemm_kernel<true, true><<<gProj, blk>>>(values,  Wv, bv, v, Mtok, Dn, INn, 0, 0, 0);

  // Scores: per batch, S[4096,4096] = q[4096,256] @ k^T
  dim3 gScores(Kn / BN, Qn / BM, Bb);
  sgemm_kernel<true, false><<<gScores, blk>>>(
      q, k, nullptr, sc, Qn, Kn, Dn,
      (long long)Qn * Dn, (long long)Kn * Dn, (long long)Qn * Kn);

  // Mask + scale + softmax (in place)
  softmax_mask_kernel<<<Mtok, 256>>>(sc, mask);

  // att: per batch, att[4096,256] = P[4096,4096] @ v[4096,256]
  dim3 gAtt(Dn / BN, Qn / BM, Bb);
  sgemm_kernel<false, false><<<gAtt, blk>>>(
      sc, v, nullptr, att, Qn, Dn, Kn,
      (long long)Qn * Kn, (long long)Kn * Dn, (long long)Qn * Dn);

  // Output projection: out[16384,256] = att @ Wo^T + bo
  sgemm_kernel<true, true><<<gProj, blk>>>(att, Wo, bo, out, Mtok, Dn, Dn, 0, 0, 0);
}

// round 4
// speedup vs baseline: 3.5888x; 3.5888x over previous
#include <cuda_runtime.h>
#include <cuda_bf16.h>
#include <cstdint>
#include <math.h>

// ---------------------------------------------------------------------------
// B=4, Q=K=4096, D=IN=256.
//   q=queries@Wq^T+bq ; k=keys@Wk^T+bk ; v=values@Wv^T+bv ; vT=v^T
//   S=q@k^T ; S=where(valid,S,-1e9)/16 ; P=softmax(S)
//   att=P@vT^T ; out=att@Wo^T+bo
// GEMMs: mma.sync m16n8k8 tf32 (fp32 accum) — works on compute_103 PTX target
// (tcgen05 requires compute_103a which this toolchain does not emit).
// ---------------------------------------------------------------------------

__device__ float g_q[4u * 4096u * 256u];
__device__ float g_k[4u * 4096u * 256u];
__device__ float g_v[4u * 4096u * 256u];
__device__ float g_vt[4u * 4096u * 256u];
__device__ float g_att[4u * 4096u * 256u];
__device__ float g_scores[67108864u];  // 4*4096*4096 fp32

// ======================= helpers =======================
__device__ __forceinline__ uint32_t smem_u32(const void* p) {
  uint32_t a;
  asm("{ .reg .u64 t; cvta.to.shared.u64 t, %1; cvt.u32.u64 %0, t; }"
      : "=r"(a) : "l"(p));
  return a;
}
__device__ __forceinline__ void cp16(uint32_t s, const void* g) {
  asm volatile("cp.async.cg.shared.global [%0], [%1], 16;\n" ::"r"(s), "l"(g));
}
__device__ __forceinline__ void cp_commit() {
  asm volatile("cp.async.commit_group;\n" ::: "memory");
}
template <int N>
__device__ __forceinline__ void cp_wait() {
  asm volatile("cp.async.wait_group %0;\n" ::"n"(N) : "memory");
}
__device__ __forceinline__ uint32_t f2tf32(float f) {
  uint32_t u;
  asm("cvt.rna.tf32.f32 %0, %1;" : "=r"(u) : "f"(f));
  return u;
}
__device__ __forceinline__ float roundtf32(float f) {
  return __uint_as_float(f2tf32(f));
}
__device__ __forceinline__ void mma8(float* d, const uint32_t* a, const uint32_t* b) {
  asm volatile(
      "mma.sync.aligned.m16n8k8.row.col.f32.tf32.tf32.f32 "
      "{%0,%1,%2,%3}, {%4,%5,%6,%7}, {%8,%9}, {%0,%1,%2,%3};"
      : "+f"(d[0]), "+f"(d[1]), "+f"(d[2]), "+f"(d[3])
      : "r"(a[0]), "r"(a[1]), "r"(a[2]), "r"(a[3]), "r"(b[0]), "r"(b[1]));
}

// ---------------------------------------------------------------------------
// tf32 tensor-core GEMM: C[M,N] = A[M,Kd] @ B[N,Kd]^T (+ bias)
// CTA tile 128x128, BK=32, 8 warps (2m x 4n), warp tile 64x32 (4x4 mma tiles).
// Smem: per stage A 128x36f + B 128x36f (stride 36 -> conflict-free fragment LDS),
// double buffered = 73728 B dynamic.
// Requires M,N % 128 == 0, Kd % 32 == 0.
// RIN:  round A/B values to tf32 (rna) after LDS (for raw-fp32 inputs).
// ROUT: round C to tf32 on store (so downstream GEMMs can skip RIN).
// ---------------------------------------------------------------------------
template <bool BIAS, bool RIN, bool ROUT>
__global__ void __launch_bounds__(256, 2) gemm_mma(
    const float* __restrict__ A, const float* __restrict__ B,
    const float* __restrict__ bias, float* __restrict__ C,
    int Kd, int ldA, int ldB, int ldC,
    long long sA, long long sB, long long sC) {
  extern __shared__ char dyn_smem[];
  const uint32_t smem_base = smem_u32(dyn_smem);
  const int tid = threadIdx.x;
  const int lane = tid & 31;
  const int wid = tid >> 5;
  const int wm = wid & 1;    // 0..1  -> 64-row half
  const int wn = wid >> 1;   // 0..3  -> 32-col quarter
  const long long z = blockIdx.z;
  const int bm = blockIdx.y * 128;
  const int bn = blockIdx.x * 128;

  const float* gA = A + z * sA + (size_t)bm * ldA;
  const float* gB = B + z * sB + (size_t)bn * ldB;

  float acc[4][4][4];
#pragma unroll
  for (int i = 0; i < 4; i++)
#pragma unroll
    for (int j = 0; j < 4; j++)
#pragma unroll
      for (int p = 0; p < 4; p++) acc[i][j][p] = 0.0f;

  const int ldRow = tid >> 3;  // 0..31
  const int ldCh = tid & 7;    // 16B chunk within 128B k-row

  auto load_tiles = [&](int stage, int k0) {
    uint32_t sa = smem_base + stage * 18432;
    uint32_t sb = smem_base + 36864 + stage * 18432;
#pragma unroll
    for (int i = 0; i < 4; i++) {
      const int row = ldRow + i * 32;
      cp16(sa + row * 144 + ldCh * 16, gA + (size_t)row * ldA + k0 + ldCh * 4);
      cp16(sb + row * 144 + ldCh * 16, gB + (size_t)row * ldB + k0 + ldCh * 4);
    }
    cp_commit();
  };

  const int r = lane >> 2;  // groupID
  const int c = lane & 3;   // threadID_in_group

  const int KT = Kd >> 5;
  load_tiles(0, 0);
  for (int it = 0; it < KT; ++it) {
    const int buf = it & 1;
    if (it + 1 < KT) {
      load_tiles(buf ^ 1, (it + 1) << 5);
      cp_wait<1>();
    } else {
      cp_wait<0>();
    }
    __syncthreads();

    const float* As = (const float*)(dyn_smem + buf * 18432);
    const float* Bs = (const float*)(dyn_smem + 36864 + buf * 18432);
    const float* aB = As + (wm * 64 + r) * 36 + c;
    const float* bB = Bs + (wn * 32 + r) * 36 + c;

#pragma unroll
    for (int ks = 0; ks < 4; ++ks) {
      uint32_t af[4][4], bf[4][2];
#pragma unroll
      for (int mt = 0; mt < 4; mt++) {
        const float* p = aB + mt * (16 * 36) + ks * 8;
        // a0:(r,c) a1:(r+8,c) a2:(r,c+4) a3:(r+8,c+4)
        float v0 = p[0], v1 = p[8 * 36], v2 = p[4], v3 = p[8 * 36 + 4];
        if (RIN) {
          af[mt][0] = f2tf32(v0); af[mt][1] = f2tf32(v1);
          af[mt][2] = f2tf32(v2); af[mt][3] = f2tf32(v3);
        } else {
          af[mt][0] = __float_as_uint(v0); af[mt][1] = __float_as_uint(v1);
          af[mt][2] = __float_as_uint(v2); af[mt][3] = __float_as_uint(v3);
        }
      }
#pragma unroll
      for (int nt = 0; nt < 4; nt++) {
        const float* p = bB + nt * (8 * 36) + ks * 8;
        // b0:(k=c, n=r)  b1:(k=c+4, n=r)
        float v0 = p[0], v1 = p[4];
        if (RIN) {
          bf[nt][0] = f2tf32(v0); bf[nt][1] = f2tf32(v1);
        } else {
          bf[nt][0] = __float_as_uint(v0); bf[nt][1] = __float_as_uint(v1);
        }
      }
#pragma unroll
      for (int mt = 0; mt < 4; mt++)
#pragma unroll
        for (int nt = 0; nt < 4; nt++) mma8(acc[mt][nt], af[mt], bf[nt]);
    }
    __syncthreads();
  }

  // Epilogue
  float* Cz = C + z * sC;
  const int c2 = (lane & 3) * 2;
#pragma unroll
  for (int mt = 0; mt < 4; mt++) {
    const int row0 = bm + wm * 64 + mt * 16 + r;
#pragma unroll
    for (int nt = 0; nt < 4; nt++) {
      const int col = bn + wn * 32 + nt * 8 + c2;
      float d0 = acc[mt][nt][0], d1 = acc[mt][nt][1];
      float d2 = acc[mt][nt][2], d3 = acc[mt][nt][3];
      if (BIAS) {
        const float b0 = bias[col], b1 = bias[col + 1];
        d0 += b0; d1 += b1; d2 += b0; d3 += b1;
      }
      if (ROUT) {
        d0 = roundtf32(d0); d1 = roundtf32(d1);
        d2 = roundtf32(d2); d3 = roundtf32(d3);
      }
      float2 v0; v0.x = d0; v0.y = d1;
      float2 v1; v1.x = d2; v1.y = d3;
      *(float2*)(Cz + (size_t)row0 * ldC + col) = v0;
      *(float2*)(Cz + (size_t)(row0 + 8) * ldC + col) = v1;
    }
  }
}

// ---------------------------------------------------------------------------
// Batched transpose: vt[b][n][k] = v[b][k][n]   (k=4096, n=256)
// ---------------------------------------------------------------------------
__global__ __launch_bounds__(256) void transpose_kernel(
    const float* __restrict__ v, float* __restrict__ vt) {
  __shared__ float t[32][33];
  const int b = blockIdx.z;
  const int k0 = blockIdx.x * 32;
  const int n0 = blockIdx.y * 32;
  const int tx = threadIdx.x & 31;
  const int ty = threadIdx.x >> 5;  // 0..7
  const float* src = v + (size_t)b * 4096 * 256;
  float* dst = vt + (size_t)b * 256 * 4096;
#pragma unroll
  for (int i = 0; i < 32; i += 8)
    t[ty + i][tx] = src[(size_t)(k0 + ty + i) * 256 + n0 + tx];
  __syncthreads();
#pragma unroll
  for (int i = 0; i < 32; i += 8)
    dst[(size_t)(n0 + ty + i) * 4096 + k0 + tx] = t[tx][ty + i];
}

// ---------------------------------------------------------------------------
// Fused length-mask + scale(1/16) + softmax, in place. Writes tf32-rounded
// probs so the PV GEMM consumes them without per-fragment cvt.
// ---------------------------------------------------------------------------
__global__ __launch_bounds__(256) void softmax_mask_kernel(
    float* __restrict__ scores, const int* __restrict__ mask) {
  const size_t row = blockIdx.x;
  const int len = mask[row];
  float* r = scores + row * 4096u;
  const int t = threadIdx.x;
  const int lane = t & 31;
  const int wid = t >> 5;

  __shared__ float sred[8];

  const float scale = 0.0625f;
  float v[16];
  float mx = -1e30f;
#pragma unroll
  for (int i = 0; i < 16; i++) {
    const int kk = t + i * 256;
    float s = (kk < len) ? r[kk] * scale : -1e30f;
    v[i] = s;
    mx = fmaxf(mx, s);
  }
#pragma unroll
  for (int o = 16; o; o >>= 1) mx = fmaxf(mx, __shfl_xor_sync(0xffffffffu, mx, o));
  if (lane == 0) sred[wid] = mx;
  __syncthreads();
  float bm = sred[0];
#pragma unroll
  for (int w = 1; w < 8; w++) bm = fmaxf(bm, sred[w]);
  __syncthreads();

  float e[16];
  float sum = 0.0f;
#pragma unroll
  for (int i = 0; i < 16; i++) {
    e[i] = __expf(v[i] - bm);
    sum += e[i];
  }
#pragma unroll
  for (int o = 16; o; o >>= 1) sum += __shfl_xor_sync(0xffffffffu, sum, o);
  if (lane == 0) sred[wid] = sum;
  __syncthreads();
  float bs = 0.0f;
#pragma unroll
  for (int w = 0; w < 8; w++) bs += sred[w];
  const float inv = 1.0f / bs;

#pragma unroll
  for (int i = 0; i < 16; i++) {
    const int kk = t + i * 256;
    r[kk] = roundtf32(e[i] * inv);
  }
}

// ---------------------------------------------------------------------------
// Launch
// ---------------------------------------------------------------------------
extern "C" void kernel_launch(void* const* d_in, const int* in_sizes, int n_in,
                              void* d_out, int out_size) {
  const float* queries = (const float*)d_in[0];
  const float* keys    = (const float*)d_in[1];
  const float* values  = (const float*)d_in[2];
  const int*   mask    = (const int*)d_in[3];
  const float* Wq = (const float*)d_in[4];
  const float* bq = (const float*)d_in[5];
  const float* Wk = (const float*)d_in[6];
  const float* bk = (const float*)d_in[7];
  const float* Wv = (const float*)d_in[8];
  const float* bv = (const float*)d_in[9];
  const float* Wo = (const float*)d_in[10];
  const float* bo = (const float*)d_in[11];
  float* out = (float*)d_out;

  float *q, *k, *v, *vt, *att, *sc;
  cudaGetSymbolAddress((void**)&q, g_q);
  cudaGetSymbolAddress((void**)&k, g_k);
  cudaGetSymbolAddress((void**)&v, g_v);
  cudaGetSymbolAddress((void**)&vt, g_vt);
  cudaGetSymbolAddress((void**)&att, g_att);
  cudaGetSymbolAddress((void**)&sc, g_scores);

  const int SMEM = 73728;
  cudaFuncSetAttribute(gemm_mma<true, true, true>,
                       cudaFuncAttributeMaxDynamicSharedMemorySize, SMEM);
  cudaFuncSetAttribute(gemm_mma<false, false, false>,
                       cudaFuncAttributeMaxDynamicSharedMemorySize, SMEM);
  cudaFuncSetAttribute(gemm_mma<true, true, false>,
                       cudaFuncAttributeMaxDynamicSharedMemorySize, SMEM);

  dim3 blk(256);
  const long long QD = 4096LL * 256;
  const long long QK = 4096LL * 4096;

  // Projections: X[16384,256] @ W[256,256]^T + b ; round in (raw fp32) and out
  dim3 gProj(2, 128, 1);
  gemm_mma<true, true, true><<<gProj, blk, SMEM>>>(
      queries, Wq, bq, q, 256, 256, 256, 256, 0, 0, 0);
  gemm_mma<true, true, true><<<gProj, blk, SMEM>>>(
      keys, Wk, bk, k, 256, 256, 256, 256, 0, 0, 0);
  gemm_mma<true, true, true><<<gProj, blk, SMEM>>>(
      values, Wv, bv, v, 256, 256, 256, 256, 0, 0, 0);

  // vT for PV GEMM (K-major B operand)
  transpose_kernel<<<dim3(128, 8, 4), blk>>>(v, vt);

  // Scores: per batch, S[4096,4096] = q @ k^T  (inputs pre-rounded, no cvt)
  gemm_mma<false, false, false><<<dim3(32, 32, 4), blk, SMEM>>>(
      q, k, nullptr, sc, 256, 256, 256, 4096, QD, QD, QK);

  // Mask + scale + softmax (in place, writes tf32-rounded probs)
  softmax_mask_kernel<<<16384, 256>>>(sc, mask);

  // att: per batch, att[4096,256] = P[4096,4096] @ vT[256,4096]^T
  gemm_mma<false, false, false><<<dim3(2, 32, 4), blk, SMEM>>>(
      sc, vt, nullptr, att, 4096, 4096, 4096, 256, QK, QD, QD);

  // Output projection: out = att @ Wo^T + bo  (Wo raw -> round inputs)
  gemm_mma<true, true, false><<<gProj, blk, SMEM>>>(
      att, Wo, bo, out, 256, 256, 256, 256, 0, 0, 0);
}